// round 16
// baseline (speedup 1.0000x reference)
#include <cuda_runtime.h>
#include <cuda_bf16.h>
#include <math_constants.h>

#define NVEC   16384
#define KCODES 8192
#define CDIM   256
#define ZELEMS (16*256*32*32)   /* 4194304 */
#define UNITS  1024             /* per-n units of 8 k */
#define MARGIN 2e-4f
#define CAND_MAX (1u<<22)

__device__ float  g_zz[NVEC];
__device__ float  g_ee[KCODES];
__device__ double g_loss;
__device__ __nv_bfloat16 g_Zh[(size_t)NVEC * CDIM];
__device__ __nv_bfloat16 g_Eh[(size_t)KCODES * CDIM];
__device__ float  g_zt[(size_t)NVEC * CDIM];     /* z transposed to [n][c], fp32 */
__device__ float  g_stmin[(size_t)NVEC * UNITS];
__device__ unsigned char g_mask[(size_t)NVEC * UNITS];
__device__ unsigned g_cand[CAND_MAX];
__device__ unsigned g_ncand;
__device__ unsigned long long g_best[NVEC];

// ---------------------------------------------------------------------------
__device__ __forceinline__ unsigned smem_u32(const void* p) {
    return (unsigned)__cvta_generic_to_shared(p);
}
__device__ __forceinline__ void ldsm4(unsigned& r0, unsigned& r1,
                                      unsigned& r2, unsigned& r3, unsigned a) {
    asm volatile("ldmatrix.sync.aligned.m8n8.x4.shared.b16 {%0,%1,%2,%3}, [%4];"
                 : "=r"(r0), "=r"(r1), "=r"(r2), "=r"(r3) : "r"(a));
}
__device__ __forceinline__ void mma16816(float* c, const unsigned* a, const unsigned* b) {
    asm volatile("mma.sync.aligned.m16n8k16.row.col.f32.bf16.bf16.f32 "
                 "{%0,%1,%2,%3},{%4,%5,%6,%7},{%8,%9},{%0,%1,%2,%3};"
                 : "+f"(c[0]), "+f"(c[1]), "+f"(c[2]), "+f"(c[3])
                 : "r"(a[0]), "r"(a[1]), "r"(a[2]), "r"(a[3]), "r"(b[0]), "r"(b[1]));
}
__device__ __forceinline__ void cp16(unsigned s, const void* g) {
    asm volatile("cp.async.cg.shared.global [%0], [%1], 16;" :: "r"(s), "l"(g));
}
__device__ __forceinline__ unsigned bf2pack(float lo, float hi) {
    __nv_bfloat162 t = __floats2bfloat162_rn(lo, hi);
    return *(unsigned*)&t;
}
__device__ __forceinline__ unsigned interleave4(unsigned a, unsigned b) {
    unsigned m = 0;
    #pragma unroll
    for (int i = 0; i < 4; i++)
        m |= (((a >> i) & 1u) << (2 * i)) | (((b >> i) & 1u) << (2 * i + 1));
    return m;
}

// ---------------------------------------------------------------------------
// prep: per-n -> zz (sequential fp32 mul+add) + bf16 Zh row + fp32 g_zt row;
//       per-k -> ee + bf16 Eh row. All row writes thread-contiguous.
// ---------------------------------------------------------------------------
__global__ void prep_kernel(const float* __restrict__ z,
                            const float* __restrict__ emb) {
    int i = blockIdx.x * 256 + threadIdx.x;
    if (i == 0) { g_loss = 0.0; g_ncand = 0u; }
    if (i < NVEC) {
        g_best[i] = 0xFFFFFFFFFFFFFFFFull;
        int b = i >> 10, hw = i & 1023;
        const float* p = z + (size_t)b * 262144 + hw;
        float acc = 0.f;
        #pragma unroll 1
        for (int ch = 0; ch < 8; ch++) {
            float v[32];
            #pragma unroll
            for (int j = 0; j < 32; j++)
                v[j] = p[(size_t)(ch * 32 + j) * 1024];
            #pragma unroll
            for (int j = 0; j < 32; j++)
                acc = __fadd_rn(acc, __fmul_rn(v[j], v[j]));
            uint4* dst = (uint4*)&g_Zh[(size_t)i * 256 + ch * 32];
            #pragma unroll
            for (int q = 0; q < 4; q++)
                dst[q] = make_uint4(bf2pack(v[q*8+0], v[q*8+1]), bf2pack(v[q*8+2], v[q*8+3]),
                                    bf2pack(v[q*8+4], v[q*8+5]), bf2pack(v[q*8+6], v[q*8+7]));
            float4* zt = (float4*)&g_zt[(size_t)i * 256 + ch * 32];
            #pragma unroll
            for (int q = 0; q < 8; q++)
                zt[q] = make_float4(v[q*4], v[q*4+1], v[q*4+2], v[q*4+3]);
        }
        g_zz[i] = acc;
    } else if (i < NVEC + KCODES) {
        int k = i - NVEC;
        const float4* p = (const float4*)(emb + (size_t)k * 256);
        float acc = 0.f;
        #pragma unroll 1
        for (int ch = 0; ch < 8; ch++) {
            float v[32];
            #pragma unroll
            for (int q = 0; q < 8; q++) {
                float4 w = p[ch * 8 + q];
                v[q*4] = w.x; v[q*4+1] = w.y; v[q*4+2] = w.z; v[q*4+3] = w.w;
            }
            #pragma unroll
            for (int j = 0; j < 32; j++)
                acc = __fadd_rn(acc, __fmul_rn(v[j], v[j]));
            uint4* dst = (uint4*)&g_Eh[(size_t)k * 256 + ch * 32];
            #pragma unroll
            for (int q = 0; q < 4; q++)
                dst[q] = make_uint4(bf2pack(v[q*8+0], v[q*8+1]), bf2pack(v[q*8+2], v[q*8+3]),
                                    bf2pack(v[q*8+4], v[q*8+5]), bf2pack(v[q*8+6], v[q*8+7]));
        }
        g_ee[k] = acc;
    }
}

// ---------------------------------------------------------------------------
// Persistent filter GEMM (mma.sync): 128 CTAs, one 128-row m-tile each.
// A (Zh tile, 64KB) resident in smem; B (Eh) streamed as 64 tiles of 128 k,
// double-buffered cp.async (pipeline fills ONCE per CTA, B is L2-resident).
// Mainloop / ldsm swizzle / epilogue mask math byte-identical to the
// verified R14 kernel -> d~ bit-identical -> identical candidate sets.
// smem: A 64KB | B0 64KB | B1 64KB | staging 10KB  = 202KB, 1 CTA/SM.
// ---------------------------------------------------------------------------
#define FSM_A   0
#define FSM_B0  65536
#define FSM_B1  131072
#define FSM_ST  196608
#define FSM_TOTAL 206848

__global__ __launch_bounds__(256, 1)
void filter_gemm_kernel() {
    extern __shared__ char sm[];
    const unsigned smb = smem_u32(sm);

    const int tid = threadIdx.x;
    const int lane = tid & 31, warp = tid >> 5;
    const int wm = warp >> 2, wn = warp & 3;
    const int n0 = blockIdx.x * 128;

    const int rA = lane & 15, cAsel = lane >> 4, l7 = lane & 7;
    const int rB = (lane & 7) + ((lane >> 4) << 3), cBsel = (lane >> 3) & 1;

    const int lrow = tid >> 3, lch = tid & 7;
    const unsigned ldst_off = (unsigned)(lrow * 128 + ((lch ^ (lrow & 7)) << 4));

    // load one 128row x 256c bf16 tile into 4 chunk-sections (16KB each),
    // section q = columns [q*64, q*64+64), row stride 128B, R14 swizzle.
    #define ISSUE_TILE(dstbase, gptr) do {                                     \
        _Pragma("unroll")                                                      \
        for (int q_ = 0; q_ < 4; q_++) {                                       \
            _Pragma("unroll")                                                  \
            for (int i_ = 0; i_ < 4; i_++) {                                   \
                int row_ = lrow + i_ * 32;                                     \
                unsigned off_ = (unsigned)(q_ * 16384) + ldst_off              \
                              + (unsigned)(i_ * 32 * 128);                     \
                cp16((dstbase) + off_,                                         \
                     (gptr) + (size_t)row_ * 256 + q_ * 64 + lch * 8);         \
            }                                                                  \
        }                                                                      \
    } while (0)

    // A resident + first B tile, one commit group
    ISSUE_TILE(smb + FSM_A, g_Zh + (size_t)n0 * 256);
    ISSUE_TILE(smb + FSM_B0, g_Eh);
    asm volatile("cp.async.commit_group;");

    // zz for this thread's fragment rows
    float zzr[4][2];
    #pragma unroll
    for (int mi = 0; mi < 4; mi++) {
        int r0 = n0 + wm * 64 + mi * 16 + (lane >> 2);
        zzr[mi][0] = g_zz[r0];
        zzr[mi][1] = g_zz[r0 + 8];
    }

    float* st = (float*)(sm + FSM_ST);                    // [128 rows][16 units]
    unsigned char* stm = (unsigned char*)(sm + FSM_ST + 8192);

    #pragma unroll 1
    for (int t = 0; t < 64; t++) {
        const int buf = t & 1;
        const unsigned bcur = smb + (buf ? FSM_B1 : FSM_B0);
        const unsigned bnxt = smb + (buf ? FSM_B0 : FSM_B1);

        __syncthreads();   // all reads of bnxt region (iter t-1) and staging flush done
        if (t < 63) {
            ISSUE_TILE(bnxt, g_Eh + (size_t)(t + 1) * 128 * 256);
            asm volatile("cp.async.commit_group;");
            asm volatile("cp.async.wait_group 1;");
        } else {
            asm volatile("cp.async.wait_group 0;");
        }
        __syncthreads();   // B[t] visible to all warps

        float acc[4][4][4];
        #pragma unroll
        for (int mi = 0; mi < 4; mi++)
            #pragma unroll
            for (int ni = 0; ni < 4; ni++)
                #pragma unroll
                for (int r = 0; r < 4; r++) acc[mi][ni][r] = 0.f;

        #pragma unroll
        for (int q = 0; q < 4; q++) {
            const unsigned Ab = smb + FSM_A + q * 16384;
            const unsigned Bb = bcur + q * 16384;
            #pragma unroll
            for (int ks = 0; ks < 4; ks++) {
                unsigned a[4][4], b[4][2];
                #pragma unroll
                for (int mi = 0; mi < 4; mi++) {
                    int row = wm * 64 + mi * 16 + rA;
                    unsigned ad = Ab + row * 128 + (((2 * ks + cAsel) ^ l7) << 4);
                    ldsm4(a[mi][0], a[mi][1], a[mi][2], a[mi][3], ad);
                }
                #pragma unroll
                for (int nj = 0; nj < 2; nj++) {
                    int row = wn * 32 + nj * 16 + rB;
                    unsigned bd = Bb + row * 128 + (((2 * ks + cBsel) ^ l7) << 4);
                    unsigned r0, r1, r2, r3;
                    ldsm4(r0, r1, r2, r3, bd);
                    b[2 * nj][0] = r0; b[2 * nj][1] = r1;
                    b[2 * nj + 1][0] = r2; b[2 * nj + 1][1] = r3;
                }
                #pragma unroll
                for (int mi = 0; mi < 4; mi++)
                    #pragma unroll
                    for (int ni = 0; ni < 4; ni++)
                        mma16816(acc[mi][ni], a[mi], b[ni]);
            }
        }

        // epilogue (identical math to R14): per-(row, 8k-unit) min + mask
        #pragma unroll
        for (int mi = 0; mi < 4; mi++) {
            int rl0 = wm * 64 + mi * 16 + (lane >> 2);
            float zz0 = zzr[mi][0], zz1 = zzr[mi][1];
            #pragma unroll
            for (int ni = 0; ni < 4; ni++) {
                int col = t * 128 + wn * 32 + ni * 8 + (lane & 3) * 2;
                float e0 = g_ee[col], e1 = g_ee[col + 1];
                float d00 = __fsub_rn(__fadd_rn(zz0, e0), __fmul_rn(2.f, acc[mi][ni][0]));
                float d01 = __fsub_rn(__fadd_rn(zz0, e1), __fmul_rn(2.f, acc[mi][ni][1]));
                float d10 = __fsub_rn(__fadd_rn(zz1, e0), __fmul_rn(2.f, acc[mi][ni][2]));
                float d11 = __fsub_rn(__fadd_rn(zz1, e1), __fmul_rn(2.f, acc[mi][ni][3]));
                float vlo = fminf(d00, d01), vhi = fminf(d10, d11);
                vlo = fminf(vlo, __shfl_xor_sync(0xffffffffu, vlo, 1));
                vlo = fminf(vlo, __shfl_xor_sync(0xffffffffu, vlo, 2));
                vhi = fminf(vhi, __shfl_xor_sync(0xffffffffu, vhi, 1));
                vhi = fminf(vhi, __shfl_xor_sync(0xffffffffu, vhi, 2));
                float thr0 = vlo + MARGIN, thr1 = vhi + MARGIN;
                unsigned b00 = __ballot_sync(0xffffffffu, d00 <= thr0);
                unsigned b01 = __ballot_sync(0xffffffffu, d01 <= thr0);
                unsigned b10 = __ballot_sync(0xffffffffu, d10 <= thr1);
                unsigned b11 = __ballot_sync(0xffffffffu, d11 <= thr1);
                if ((lane & 3) == 0) {
                    int g4 = lane & ~3;
                    unsigned m0 = interleave4((b00 >> g4) & 0xF, (b01 >> g4) & 0xF);
                    unsigned m1 = interleave4((b10 >> g4) & 0xF, (b11 >> g4) & 0xF);
                    st[rl0 * 16 + wn * 4 + ni] = vlo;
                    st[(rl0 + 8) * 16 + wn * 4 + ni] = vhi;
                    stm[rl0 * 16 + wn * 4 + ni] = (unsigned char)m0;
                    stm[(rl0 + 8) * 16 + wn * 4 + ni] = (unsigned char)m1;
                }
            }
        }
        __syncthreads();
        {
            int rl = tid >> 1, u0 = (tid & 1) * 8;
            float* dst = &g_stmin[(size_t)(n0 + rl) * UNITS + t * 16 + u0];
            float* src = &st[rl * 16 + u0];
            *(float4*)dst = *(float4*)src;
            *(float4*)(dst + 4) = *(float4*)(src + 4);
            *(unsigned long long*)&g_mask[(size_t)(n0 + rl) * UNITS + t * 16 + u0] =
                *(unsigned long long*)&stm[rl * 16 + u0];
        }
    }
    #undef ISSUE_TILE
}

// ---------------------------------------------------------------------------
// Extraction: warp per n. Global min over 1024 unit-mins, flag units within
// MARGIN, emit individual k candidates from per-unit masks: (n<<13 | k).
// ---------------------------------------------------------------------------
__global__ __launch_bounds__(256)
void extract_kernel() {
    int n = (blockIdx.x * 256 + threadIdx.x) >> 5;
    int lane = threadIdx.x & 31;
    if (n >= NVEC) return;
    const float4* row = (const float4*)&g_stmin[(size_t)n * UNITS];
    const unsigned* m32 = (const unsigned*)&g_mask[(size_t)n * UNITS];

    float4 v[8]; unsigned mk[8];
    float mn = CUDART_INF_F;
    #pragma unroll
    for (int j = 0; j < 8; j++) {
        v[j] = row[j * 32 + lane];
        mk[j] = m32[j * 32 + lane];
        mn = fminf(mn, fminf(fminf(v[j].x, v[j].y), fminf(v[j].z, v[j].w)));
    }
    #pragma unroll
    for (int o = 16; o; o >>= 1) mn = fminf(mn, __shfl_xor_sync(0xffffffffu, mn, o));
    const float thr = mn + MARGIN;

    unsigned cnt = 0;
    #pragma unroll
    for (int j = 0; j < 8; j++) {
        float vv[4] = { v[j].x, v[j].y, v[j].z, v[j].w };
        #pragma unroll
        for (int c = 0; c < 4; c++)
            if (vv[c] <= thr) cnt += __popc((mk[j] >> (8 * c)) & 0xFFu);
    }

    unsigned p = cnt;
    #pragma unroll
    for (int o = 1; o < 32; o <<= 1) {
        unsigned tv = __shfl_up_sync(0xffffffffu, p, o);
        if (lane >= o) p += tv;
    }
    unsigned excl = p - cnt;
    unsigned total = __shfl_sync(0xffffffffu, p, 31);
    unsigned base = 0;
    if (lane == 31) base = atomicAdd(&g_ncand, total);
    base = __shfl_sync(0xffffffffu, base, 31);

    unsigned w = base + excl;
    #pragma unroll
    for (int j = 0; j < 8; j++) {
        float vv[4] = { v[j].x, v[j].y, v[j].z, v[j].w };
        #pragma unroll
        for (int c = 0; c < 4; c++) {
            if (vv[c] <= thr) {
                unsigned unit = (unsigned)((j * 32 + lane) * 4 + c);
                unsigned bits = (mk[j] >> (8 * c)) & 0xFFu;
                while (bits) {
                    int bbit = __ffs(bits) - 1;
                    bits &= bits - 1;
                    if (w < CAND_MAX)
                        g_cand[w++] = ((unsigned)n << 13) | (unit * 8 + bbit);
                }
            }
        }
    }
}

// ---------------------------------------------------------------------------
// Rescore: one candidate (n, k) per thread. Bit-exact sequential fma chain.
// ---------------------------------------------------------------------------
#define RS_BLOCKS 592
__global__ __launch_bounds__(256)
void rescore_kernel(const float* __restrict__ emb) {
    unsigned idx = blockIdx.x * 256 + threadIdx.x;
    unsigned stride = gridDim.x * 256;
    const unsigned ncand = g_ncand;

    for (unsigned ci = idx; ci < ncand; ci += stride) {
        unsigned cd = g_cand[ci];
        int n = cd >> 13, k = cd & 8191;

        const float4* zr = (const float4*)&g_zt[(size_t)n * 256];
        const float4* er = (const float4*)&emb[(size_t)k * 256];
        float acc = 0.f;
        #pragma unroll 8
        for (int c4 = 0; c4 < 64; c4++) {
            float4 zf = zr[c4];
            float4 ef = er[c4];
            acc = fmaf(zf.x, ef.x, acc);
            acc = fmaf(zf.y, ef.y, acc);
            acc = fmaf(zf.z, ef.z, acc);
            acc = fmaf(zf.w, ef.w, acc);
        }
        float d = __fsub_rn(__fadd_rn(g_zz[n], g_ee[k]), __fmul_rn(2.f, acc));
        unsigned long long key =
            ((unsigned long long)__float_as_uint(d) << 32) | (unsigned)k;
        atomicMin(&g_best[n], key);
    }
}

// ---------------------------------------------------------------------------
// finish (fused gather): out[o] = fl(z + fl(zq - z)) via 32x32 smem transpose
// tile, gathering zq rows directly from emb[g_best[n]]. loss via double atomics.
// ---------------------------------------------------------------------------
__global__ __launch_bounds__(256)
void finish_kernel(const float* __restrict__ z, const float* __restrict__ emb,
                   float* __restrict__ out) {
    __shared__ float s[32 * 33];
    const int bid = blockIdx.x;
    const int b = bid >> 8, ct = (bid >> 5) & 7, ht = bid & 31;
    const int c0 = ct * 32, hw0 = ht * 32;
    const int t = threadIdx.x;

    {   // gather zq tile [32 hw rows][32 c] from emb rows
        int r = t >> 3, q4 = t & 7;
        int n = b * 1024 + hw0 + r;
        unsigned k = (unsigned)(g_best[n] & 0xFFFFFFFFull);
        float4 w = *(const float4*)&emb[(size_t)k * 256 + c0 + q4 * 4];
        float* d = &s[r * 33 + q4 * 4];
        d[0] = w.x; d[1] = w.y; d[2] = w.z; d[3] = w.w;
    }
    __syncthreads();

    const int hwl = t & 31, cl0 = t >> 5;
    float d2s = 0.f;
    #pragma unroll
    for (int it = 0; it < 4; it++) {
        int cl = cl0 + it * 8;
        size_t o = (size_t)b * 262144 + (size_t)(c0 + cl) * 1024 + hw0 + hwl;
        float zv = z[o];
        float q  = s[hwl * 33 + cl];
        float diff = __fsub_rn(q, zv);
        out[o] = __fadd_rn(zv, diff);
        d2s += __fmul_rn(diff, diff);
    }

    #pragma unroll
    for (int off = 16; off; off >>= 1)
        d2s += __shfl_xor_sync(0xffffffffu, d2s, off);
    __shared__ float red[8];
    if ((t & 31) == 0) red[t >> 5] = d2s;
    __syncthreads();
    if (t < 8) {
        float v = red[t];
        #pragma unroll
        for (int off = 4; off; off >>= 1)
            v += __shfl_xor_sync(0xffu, v, off);
        if (t == 0) atomicAdd(&g_loss, (double)v);
    }
}

__global__ void tail_kernel(float* __restrict__ out, int out_size) {
    int i = blockIdx.x * 256 + threadIdx.x;
    if (i < NVEC && out_size >= ZELEMS + NVEC)
        out[ZELEMS + i] = (float)(unsigned)(g_best[i] & 0xFFFFFFFFull);
    if (i == 0 && out_size >= ZELEMS + NVEC + 1) {
        float m = (float)(g_loss / (double)ZELEMS);
        out[ZELEMS + NVEC] = __fadd_rn(m, __fmul_rn(0.25f, m)); // m + BETA*m
    }
}

// ---------------------------------------------------------------------------
extern "C" void kernel_launch(void* const* d_in, const int* in_sizes, int n_in,
                              void* d_out, int out_size) {
    const float* z   = (const float*)d_in[0];
    const float* emb = (const float*)d_in[1];
    float* out = (float*)d_out;

    cudaFuncSetAttribute(filter_gemm_kernel,
                         cudaFuncAttributeMaxDynamicSharedMemorySize, FSM_TOTAL);

    prep_kernel<<<(NVEC + KCODES + 255) / 256, 256>>>(z, emb);
    filter_gemm_kernel<<<128, 256, FSM_TOTAL>>>();
    extract_kernel<<<NVEC * 32 / 256, 256>>>();
    rescore_kernel<<<RS_BLOCKS, 256>>>(emb);
    finish_kernel<<<16 * 8 * 32, 256>>>(z, emb, out);
    tail_kernel<<<(NVEC + 255) / 256, 256>>>(out, out_size);
}

// round 17
// speedup vs baseline: 1.4159x; 1.4159x over previous
#include <cuda_runtime.h>
#include <cuda_bf16.h>
#include <math_constants.h>

#define NVEC   16384
#define KCODES 8192
#define CDIM   256
#define ZELEMS (16*256*32*32)   /* 4194304 */
#define UNITS  1024             /* per-n units of 8 k */
#define MARGIN 2e-4f
#define CAND_MAX (1u<<22)

__device__ float  g_zz[NVEC];
__device__ float  g_ee[KCODES];
__device__ double g_loss;
__device__ __nv_bfloat16 g_Zh[(size_t)NVEC * CDIM];
__device__ __nv_bfloat16 g_Eh[(size_t)KCODES * CDIM];
__device__ float  g_zt[(size_t)NVEC * CDIM];     /* z transposed to [n][c], fp32 */
__device__ float  g_stmin[(size_t)NVEC * UNITS];
__device__ unsigned char g_mask[(size_t)NVEC * UNITS];
__device__ unsigned g_cand[CAND_MAX];
__device__ unsigned g_ncand;
__device__ unsigned long long g_best[NVEC];

// ---------------------------------------------------------------------------
__device__ __forceinline__ unsigned smem_u32(const void* p) {
    return (unsigned)__cvta_generic_to_shared(p);
}
__device__ __forceinline__ void ldsm4(unsigned& r0, unsigned& r1,
                                      unsigned& r2, unsigned& r3, unsigned a) {
    asm volatile("ldmatrix.sync.aligned.m8n8.x4.shared.b16 {%0,%1,%2,%3}, [%4];"
                 : "=r"(r0), "=r"(r1), "=r"(r2), "=r"(r3) : "r"(a));
}
__device__ __forceinline__ void mma16816(float* c, const unsigned* a, const unsigned* b) {
    asm volatile("mma.sync.aligned.m16n8k16.row.col.f32.bf16.bf16.f32 "
                 "{%0,%1,%2,%3},{%4,%5,%6,%7},{%8,%9},{%0,%1,%2,%3};"
                 : "+f"(c[0]), "+f"(c[1]), "+f"(c[2]), "+f"(c[3])
                 : "r"(a[0]), "r"(a[1]), "r"(a[2]), "r"(a[3]), "r"(b[0]), "r"(b[1]));
}
__device__ __forceinline__ void cp16(unsigned s, const void* g) {
    asm volatile("cp.async.cg.shared.global [%0], [%1], 16;" :: "r"(s), "l"(g));
}
__device__ __forceinline__ unsigned bf2pack(float lo, float hi) {
    __nv_bfloat162 t = __floats2bfloat162_rn(lo, hi);
    return *(unsigned*)&t;
}

// ---------------------------------------------------------------------------
// prep: per-n -> zz (sequential fp32 mul+add) + bf16 Zh row + fp32 g_zt row;
//       per-k -> ee + bf16 Eh row. All row writes thread-contiguous.
// ---------------------------------------------------------------------------
__global__ void prep_kernel(const float* __restrict__ z,
                            const float* __restrict__ emb) {
    int i = blockIdx.x * 256 + threadIdx.x;
    if (i == 0) { g_loss = 0.0; g_ncand = 0u; }
    if (i < NVEC) {
        g_best[i] = 0xFFFFFFFFFFFFFFFFull;
        int b = i >> 10, hw = i & 1023;
        const float* p = z + (size_t)b * 262144 + hw;
        float acc = 0.f;
        #pragma unroll 1
        for (int ch = 0; ch < 8; ch++) {
            float v[32];
            #pragma unroll
            for (int j = 0; j < 32; j++)
                v[j] = p[(size_t)(ch * 32 + j) * 1024];
            #pragma unroll
            for (int j = 0; j < 32; j++)
                acc = __fadd_rn(acc, __fmul_rn(v[j], v[j]));
            uint4* dst = (uint4*)&g_Zh[(size_t)i * 256 + ch * 32];
            #pragma unroll
            for (int q = 0; q < 4; q++)
                dst[q] = make_uint4(bf2pack(v[q*8+0], v[q*8+1]), bf2pack(v[q*8+2], v[q*8+3]),
                                    bf2pack(v[q*8+4], v[q*8+5]), bf2pack(v[q*8+6], v[q*8+7]));
            float4* zt = (float4*)&g_zt[(size_t)i * 256 + ch * 32];
            #pragma unroll
            for (int q = 0; q < 8; q++)
                zt[q] = make_float4(v[q*4], v[q*4+1], v[q*4+2], v[q*4+3]);
        }
        g_zz[i] = acc;
    } else if (i < NVEC + KCODES) {
        int k = i - NVEC;
        const float4* p = (const float4*)(emb + (size_t)k * 256);
        float acc = 0.f;
        #pragma unroll 1
        for (int ch = 0; ch < 8; ch++) {
            float v[32];
            #pragma unroll
            for (int q = 0; q < 8; q++) {
                float4 w = p[ch * 8 + q];
                v[q*4] = w.x; v[q*4+1] = w.y; v[q*4+2] = w.z; v[q*4+3] = w.w;
            }
            #pragma unroll
            for (int j = 0; j < 32; j++)
                acc = __fadd_rn(acc, __fmul_rn(v[j], v[j]));
            uint4* dst = (uint4*)&g_Eh[(size_t)k * 256 + ch * 32];
            #pragma unroll
            for (int q = 0; q < 4; q++)
                dst[q] = make_uint4(bf2pack(v[q*8+0], v[q*8+1]), bf2pack(v[q*8+2], v[q*8+3]),
                                    bf2pack(v[q*8+4], v[q*8+5]), bf2pack(v[q*8+6], v[q*8+7]));
        }
        g_ee[k] = acc;
    }
}

// ---------------------------------------------------------------------------
// Filter GEMM: dot~ = Zh*Eh (K=256), fp32 acc. CTA 128n x 128k, 8 warps (2x4),
// warp 64x32, mma m16n8k16. 3-stage cp.async circular pipeline, 1 sync/chunk.
// Epilogue: per-(row, 8k-unit) min + per-unit 8-bit mask of k's with
// d~ <= unit_min + MARGIN. Mask encoding: low nibble bit i = col 2i,
// high nibble bit i = col 2i+1 (extract remaps) -> NO interleave ALU cost.
// ---------------------------------------------------------------------------
__global__ __launch_bounds__(256, 2)
void filter_gemm_kernel() {
    extern __shared__ char sm[];
    const unsigned smBase = smem_u32(sm);

    const int t = threadIdx.x;
    const int lane = t & 31, warp = t >> 5;
    const int wm = warp >> 2, wn = warp & 3;
    const int bm = blockIdx.x >> 6, bn = blockIdx.x & 63;

    float acc[4][4][4];
    #pragma unroll
    for (int mi = 0; mi < 4; mi++)
        #pragma unroll
        for (int ni = 0; ni < 4; ni++)
            #pragma unroll
            for (int r = 0; r < 4; r++) acc[mi][ni][r] = 0.f;

    const int rA = lane & 15, cAsel = lane >> 4, l7 = lane & 7;
    const int rB = (lane & 7) + ((lane >> 4) << 3), cBsel = (lane >> 3) & 1;

    const int lrow = t >> 3, lch = t & 7;
    const unsigned ldst_off = (unsigned)(lrow * 128 + ((lch ^ (lrow & 7)) << 4));

    #define ISSUE_CHUNK(q, s) do {                                            \
        int coff_ = (q) * 64;                                                  \
        _Pragma("unroll")                                                      \
        for (int i_ = 0; i_ < 4; i_++) {                                       \
            int row_ = lrow + i_ * 32;                                         \
            unsigned off_ = ldst_off + i_ * 32 * 128;                          \
            cp16(smBase + (s) * 32768 + off_,                                  \
                 g_Zh + (size_t)(bm * 128 + row_) * 256 + coff_ + lch * 8);    \
            cp16(smBase + (s) * 32768 + 16384 + off_,                          \
                 g_Eh + (size_t)(bn * 128 + row_) * 256 + coff_ + lch * 8);    \
        }                                                                      \
        asm volatile("cp.async.commit_group;");                                \
    } while (0)

    ISSUE_CHUNK(0, 0);
    ISSUE_CHUNK(1, 1);

    #pragma unroll
    for (int q = 0; q < 4; q++) {
        if (q < 3) asm volatile("cp.async.wait_group 1;");
        else       asm volatile("cp.async.wait_group 0;");
        __syncthreads();

        const unsigned Ab = smBase + (q % 3) * 32768;
        const unsigned Bb = Ab + 16384;

        #pragma unroll
        for (int ks = 0; ks < 4; ks++) {
            unsigned a[4][4], b[4][2];
            #pragma unroll
            for (int mi = 0; mi < 4; mi++) {
                int row = wm * 64 + mi * 16 + rA;
                unsigned ad = Ab + row * 128 + (((2 * ks + cAsel) ^ l7) << 4);
                ldsm4(a[mi][0], a[mi][1], a[mi][2], a[mi][3], ad);
            }
            #pragma unroll
            for (int nj = 0; nj < 2; nj++) {
                int row = wn * 32 + nj * 16 + rB;
                unsigned bd = Bb + row * 128 + (((2 * ks + cBsel) ^ l7) << 4);
                unsigned r0, r1, r2, r3;
                ldsm4(r0, r1, r2, r3, bd);
                b[2 * nj][0] = r0; b[2 * nj][1] = r1;
                b[2 * nj + 1][0] = r2; b[2 * nj + 1][1] = r3;
            }
            #pragma unroll
            for (int mi = 0; mi < 4; mi++)
                #pragma unroll
                for (int ni = 0; ni < 4; ni++)
                    mma16816(acc[mi][ni], a[mi], b[ni]);
        }
        if (q < 2) ISSUE_CHUNK(q + 2, (q + 2) % 3);
    }

    __syncthreads();
    float* st = (float*)sm;                              // [128 rows][16 units]
    unsigned char* stm = (unsigned char*)(sm + 8192);    // [128 rows][16 units]

    // hoist e-norms (depend on ni, lane only)
    float ev[4][2];
    #pragma unroll
    for (int ni = 0; ni < 4; ni++) {
        int col = bn * 128 + wn * 32 + ni * 8 + (lane & 3) * 2;
        ev[ni][0] = g_ee[col];
        ev[ni][1] = g_ee[col + 1];
    }
    const int g4 = lane & ~3;

    #pragma unroll
    for (int mi = 0; mi < 4; mi++) {
        int rl0 = wm * 64 + mi * 16 + (lane >> 2);
        int r0 = bm * 128 + rl0;
        float zz0 = g_zz[r0], zz1 = g_zz[r0 + 8];
        #pragma unroll
        for (int ni = 0; ni < 4; ni++) {
            float e0 = ev[ni][0], e1 = ev[ni][1];
            float d00 = __fsub_rn(__fadd_rn(zz0, e0), __fmul_rn(2.f, acc[mi][ni][0]));
            float d01 = __fsub_rn(__fadd_rn(zz0, e1), __fmul_rn(2.f, acc[mi][ni][1]));
            float d10 = __fsub_rn(__fadd_rn(zz1, e0), __fmul_rn(2.f, acc[mi][ni][2]));
            float d11 = __fsub_rn(__fadd_rn(zz1, e1), __fmul_rn(2.f, acc[mi][ni][3]));
            float vlo = fminf(d00, d01), vhi = fminf(d10, d11);
            vlo = fminf(vlo, __shfl_xor_sync(0xffffffffu, vlo, 1));
            vlo = fminf(vlo, __shfl_xor_sync(0xffffffffu, vlo, 2));
            vhi = fminf(vhi, __shfl_xor_sync(0xffffffffu, vhi, 1));
            vhi = fminf(vhi, __shfl_xor_sync(0xffffffffu, vhi, 2));
            float thr0 = vlo + MARGIN, thr1 = vhi + MARGIN;
            unsigned b00 = __ballot_sync(0xffffffffu, d00 <= thr0);
            unsigned b01 = __ballot_sync(0xffffffffu, d01 <= thr0);
            unsigned b10 = __ballot_sync(0xffffffffu, d10 <= thr1);
            unsigned b11 = __ballot_sync(0xffffffffu, d11 <= thr1);
            if ((lane & 3) == 0) {
                // nibble-pack: low nibble = even cols, high nibble = odd cols
                unsigned m0 = ((b00 >> g4) & 0xFu) | (((b01 >> g4) & 0xFu) << 4);
                unsigned m1 = ((b10 >> g4) & 0xFu) | (((b11 >> g4) & 0xFu) << 4);
                st[rl0 * 16 + wn * 4 + ni] = vlo;
                st[(rl0 + 8) * 16 + wn * 4 + ni] = vhi;
                stm[rl0 * 16 + wn * 4 + ni] = (unsigned char)m0;
                stm[(rl0 + 8) * 16 + wn * 4 + ni] = (unsigned char)m1;
            }
        }
    }
    __syncthreads();
    {
        int rl = t >> 1, u0 = (t & 1) * 8;
        float* dst = &g_stmin[(size_t)(bm * 128 + rl) * UNITS + bn * 16 + u0];
        float* src = &st[rl * 16 + u0];
        *(float4*)dst = *(float4*)src;
        *(float4*)(dst + 4) = *(float4*)(src + 4);
        *(unsigned long long*)&g_mask[(size_t)(bm * 128 + rl) * UNITS + bn * 16 + u0] =
            *(unsigned long long*)&stm[rl * 16 + u0];
    }
}

// ---------------------------------------------------------------------------
// Extraction: warp per n. Global min over 1024 unit-mins, flag units within
// MARGIN, emit individual k candidates from per-unit masks: (n<<13 | k).
// Mask decode: bit b -> col offset ((b&3)<<1) | (b>>2)   (nibble encoding).
// ---------------------------------------------------------------------------
__global__ __launch_bounds__(256)
void extract_kernel() {
    int n = (blockIdx.x * 256 + threadIdx.x) >> 5;
    int lane = threadIdx.x & 31;
    if (n >= NVEC) return;
    const float4* row = (const float4*)&g_stmin[(size_t)n * UNITS];
    const unsigned* m32 = (const unsigned*)&g_mask[(size_t)n * UNITS];

    float4 v[8]; unsigned mk[8];
    float mn = CUDART_INF_F;
    #pragma unroll
    for (int j = 0; j < 8; j++) {
        v[j] = row[j * 32 + lane];
        mk[j] = m32[j * 32 + lane];
        mn = fminf(mn, fminf(fminf(v[j].x, v[j].y), fminf(v[j].z, v[j].w)));
    }
    #pragma unroll
    for (int o = 16; o; o >>= 1) mn = fminf(mn, __shfl_xor_sync(0xffffffffu, mn, o));
    const float thr = mn + MARGIN;

    unsigned cnt = 0;
    #pragma unroll
    for (int j = 0; j < 8; j++) {
        float vv[4] = { v[j].x, v[j].y, v[j].z, v[j].w };
        #pragma unroll
        for (int c = 0; c < 4; c++)
            if (vv[c] <= thr) cnt += __popc((mk[j] >> (8 * c)) & 0xFFu);
    }

    unsigned p = cnt;
    #pragma unroll
    for (int o = 1; o < 32; o <<= 1) {
        unsigned tv = __shfl_up_sync(0xffffffffu, p, o);
        if (lane >= o) p += tv;
    }
    unsigned excl = p - cnt;
    unsigned total = __shfl_sync(0xffffffffu, p, 31);
    unsigned base = 0;
    if (lane == 31) base = atomicAdd(&g_ncand, total);
    base = __shfl_sync(0xffffffffu, base, 31);

    unsigned w = base + excl;
    #pragma unroll
    for (int j = 0; j < 8; j++) {
        float vv[4] = { v[j].x, v[j].y, v[j].z, v[j].w };
        #pragma unroll
        for (int c = 0; c < 4; c++) {
            if (vv[c] <= thr) {
                unsigned unit = (unsigned)((j * 32 + lane) * 4 + c);
                unsigned bits = (mk[j] >> (8 * c)) & 0xFFu;
                while (bits) {
                    unsigned bbit = (unsigned)(__ffs(bits) - 1);
                    bits &= bits - 1;
                    unsigned off = ((bbit & 3u) << 1) | (bbit >> 2);
                    if (w < CAND_MAX)
                        g_cand[w++] = ((unsigned)n << 13) | (unit * 8 + off);
                }
            }
        }
    }
}

// ---------------------------------------------------------------------------
// Rescore: one candidate (n, k) per thread. Bit-exact sequential fma chain.
// ---------------------------------------------------------------------------
#define RS_BLOCKS 592
__global__ __launch_bounds__(256)
void rescore_kernel(const float* __restrict__ emb) {
    unsigned idx = blockIdx.x * 256 + threadIdx.x;
    unsigned stride = gridDim.x * 256;
    const unsigned ncand = g_ncand;

    for (unsigned ci = idx; ci < ncand; ci += stride) {
        unsigned cd = g_cand[ci];
        int n = cd >> 13, k = cd & 8191;

        const float4* zr = (const float4*)&g_zt[(size_t)n * 256];
        const float4* er = (const float4*)&emb[(size_t)k * 256];
        float acc = 0.f;
        #pragma unroll 8
        for (int c4 = 0; c4 < 64; c4++) {
            float4 zf = zr[c4];
            float4 ef = er[c4];
            acc = fmaf(zf.x, ef.x, acc);
            acc = fmaf(zf.y, ef.y, acc);
            acc = fmaf(zf.z, ef.z, acc);
            acc = fmaf(zf.w, ef.w, acc);
        }
        float d = __fsub_rn(__fadd_rn(g_zz[n], g_ee[k]), __fmul_rn(2.f, acc));
        unsigned long long key =
            ((unsigned long long)__float_as_uint(d) << 32) | (unsigned)k;
        atomicMin(&g_best[n], key);
    }
}

// ---------------------------------------------------------------------------
// finish (fused gather): out[o] = fl(z + fl(zq - z)) via 32x32 smem transpose
// tile, gathering zq rows directly from emb[g_best[n]]. loss via double atomics.
// ---------------------------------------------------------------------------
__global__ __launch_bounds__(256)
void finish_kernel(const float* __restrict__ z, const float* __restrict__ emb,
                   float* __restrict__ out) {
    __shared__ float s[32 * 33];
    const int bid = blockIdx.x;
    const int b = bid >> 8, ct = (bid >> 5) & 7, ht = bid & 31;
    const int c0 = ct * 32, hw0 = ht * 32;
    const int t = threadIdx.x;

    {   // gather zq tile [32 hw rows][32 c] from emb rows
        int r = t >> 3, q4 = t & 7;
        int n = b * 1024 + hw0 + r;
        unsigned k = (unsigned)(g_best[n] & 0xFFFFFFFFull);
        float4 w = *(const float4*)&emb[(size_t)k * 256 + c0 + q4 * 4];
        float* d = &s[r * 33 + q4 * 4];
        d[0] = w.x; d[1] = w.y; d[2] = w.z; d[3] = w.w;
    }
    __syncthreads();

    const int hwl = t & 31, cl0 = t >> 5;
    float d2s = 0.f;
    #pragma unroll
    for (int it = 0; it < 4; it++) {
        int cl = cl0 + it * 8;
        size_t o = (size_t)b * 262144 + (size_t)(c0 + cl) * 1024 + hw0 + hwl;
        float zv = z[o];
        float q  = s[hwl * 33 + cl];
        float diff = __fsub_rn(q, zv);
        out[o] = __fadd_rn(zv, diff);
        d2s += __fmul_rn(diff, diff);
    }

    #pragma unroll
    for (int off = 16; off; off >>= 1)
        d2s += __shfl_xor_sync(0xffffffffu, d2s, off);
    __shared__ float red[8];
    if ((t & 31) == 0) red[t >> 5] = d2s;
    __syncthreads();
    if (t < 8) {
        float v = red[t];
        #pragma unroll
        for (int off = 4; off; off >>= 1)
            v += __shfl_xor_sync(0xffu, v, off);
        if (t == 0) atomicAdd(&g_loss, (double)v);
    }
}

__global__ void tail_kernel(float* __restrict__ out, int out_size) {
    int i = blockIdx.x * 256 + threadIdx.x;
    if (i < NVEC && out_size >= ZELEMS + NVEC)
        out[ZELEMS + i] = (float)(unsigned)(g_best[i] & 0xFFFFFFFFull);
    if (i == 0 && out_size >= ZELEMS + NVEC + 1) {
        float m = (float)(g_loss / (double)ZELEMS);
        out[ZELEMS + NVEC] = __fadd_rn(m, __fmul_rn(0.25f, m)); // m + BETA*m
    }
}

// ---------------------------------------------------------------------------
extern "C" void kernel_launch(void* const* d_in, const int* in_sizes, int n_in,
                              void* d_out, int out_size) {
    const float* z   = (const float*)d_in[0];
    const float* emb = (const float*)d_in[1];
    float* out = (float*)d_out;

    cudaFuncSetAttribute(filter_gemm_kernel,
                         cudaFuncAttributeMaxDynamicSharedMemorySize, 98304);

    prep_kernel<<<(NVEC + KCODES + 255) / 256, 256>>>(z, emb);
    filter_gemm_kernel<<<128 * 64, 256, 98304>>>();
    extract_kernel<<<NVEC * 32 / 256, 256>>>();
    rescore_kernel<<<RS_BLOCKS, 256>>>(emb);
    finish_kernel<<<16 * 8 * 32, 256>>>(z, emb, out);
    tail_kernel<<<(NVEC + 255) / 256, 256>>>(out, out_size);
}